// round 2
// baseline (speedup 1.0000x reference)
#include <cuda_runtime.h>

// Problem dims
#define T_STEPS 32
#define NB      16
#define CIN     2
#define COUT    8
#define HH      128
#define WW      128
#define KK      5
#define PADL    2
#define HP      (HH + 2*PADL)   // 132
#define WP      (WW + 2*PADL)   // 132
#define NW      (COUT*CIN*KK*KK) // 400

// Tiling
#define TH 8
#define TW 32
#define PH (TH + 4)  // 12
#define PW (TW + 4)  // 36
#define NBLK ((WW/TW) * (HH/TH) * NB)  // 4*16*16 = 1024

// Persistent state (device globals: allocation-free)
__device__ float g_v[NB*COUT*HH*WW];          // membrane potential
__device__ float g_tp[NB*COUT*HH*WW];         // post trace
__device__ float g_trpre[2][NB*CIN*HP*WP];    // pre trace (padded grid), double buffered
__device__ float g_w[NW];                     // current weights
__device__ float g_part[NW * NBLK];           // per-block dw partials (deterministic reduce)

__global__ void k_init(const float* __restrict__ w0) {
    int idx = blockIdx.x * blockDim.x + threadIdx.x;
    int stride = gridDim.x * blockDim.x;
    for (int i = idx; i < NB*COUT*HH*WW; i += stride) { g_v[i] = 0.f; g_tp[i] = 0.f; }
    for (int i = idx; i < NB*CIN*HP*WP; i += stride) { g_trpre[0][i] = 0.f; g_trpre[1][i] = 0.f; }
    if (idx < NW) g_w[idx] = w0[idx];
}

// One simulation step: conv + LIF + spike out + trace updates + dw partials.
__global__ __launch_bounds__(256)
void k_step(const float* __restrict__ x_seq, float* __restrict__ out, int t, int cur) {
    __shared__ float xs [CIN][PH][PW];   // x_pad patch (0/1)
    __shared__ float trn[CIN][PH][PW];   // NEW pre-trace patch
    __shared__ float tp_s[TH*TW][COUT];  // NEW post trace per tile pixel
    __shared__ float sp_s[TH*TW][COUT];  // spikes per tile pixel
    __shared__ float w_s[NW];
    __shared__ float red[NW*3];          // partials per row-chunk

    const int tid = threadIdx.x;
    const int b   = blockIdx.z;
    const int ty0 = blockIdx.y * TH;
    const int tx0 = blockIdx.x * TW;

    for (int j = tid; j < NW; j += 256) w_s[j] = g_w[j];

    const float* xt  = x_seq + (((size_t)t*NB + b) * CIN) * HH * WW;
    const float* tro = g_trpre[cur]     + (size_t)b * CIN * HP * WP;
    float*       trw = g_trpre[cur ^ 1] + (size_t)b * CIN * HP * WP;

    // Ownership of padded-grid cells: interior tiles own TH x TW; the last
    // row/col tiles also own the trailing 4-wide border strip.
    const int ownH = (ty0 + TH == HH) ? PH : TH;
    const int ownW = (tx0 + TW == WW) ? PW : TW;

    // Load x patch, compute new pre-trace (trn = old - old/30 + x_pad), write owned region.
    for (int idx = tid; idx < CIN*PH*PW; idx += 256) {
        int i   = idx / (PH*PW);
        int rem = idx % (PH*PW);
        int r = rem / PW, c = rem % PW;
        int u = ty0 + r, vv = tx0 + c;         // padded-grid coords
        int xr = u - PADL, xc = vv - PADL;
        float xv = 0.f;
        if (xr >= 0 && xr < HH && xc >= 0 && xc < WW)
            xv = xt[(i*HH + xr)*WW + xc];
        xs[i][r][c] = xv;
        float to = tro[(i*HP + u)*WP + vv];
        float tn = to - to / 30.0f + xv;
        trn[i][r][c] = tn;
        if (r < ownH && c < ownW)
            trw[(i*HP + u)*WP + vv] = tn;
    }
    __syncthreads();

    // Phase 1: conv + LIF + traces. One pixel per thread (256 px per tile).
    {
        const int p  = tid;
        const int px = p >> 5;        // TW == 32
        const int py = p & 31;
        float y[COUT];
        #pragma unroll
        for (int o = 0; o < COUT; o++) y[o] = 0.f;

        #pragma unroll
        for (int i = 0; i < CIN; i++)
            #pragma unroll
            for (int kh = 0; kh < KK; kh++)
                #pragma unroll
                for (int kw = 0; kw < KK; kw++) {
                    float xv = xs[i][px + kh][py + kw];
                    #pragma unroll
                    for (int o = 0; o < COUT; o++)
                        y[o] += xv * w_s[((o*CIN + i)*KK + kh)*KK + kw];
                }

        const int gx = ty0 + px, gy = tx0 + py;
        const size_t base = (size_t)b * COUT * HH * WW + (size_t)gx * WW + gy;
        float* outp = out + ((size_t)t * NB + b) * COUT * HH * WW + (size_t)gx * WW + gy;
        #pragma unroll
        for (int o = 0; o < COUT; o++) {
            size_t gi = base + (size_t)o * HH * WW;
            float v = g_v[gi];
            v = v + (y[o] - v) / 100.0f;           // LIF charge (decay_input)
            float s = (v >= 1.0f) ? 1.f : 0.f;     // fire
            v = v * (1.f - s);                     // hard reset
            g_v[gi] = v;
            float tpv = g_tp[gi];
            tpv = tpv - tpv / 30.0f + s;           // post trace
            g_tp[gi] = tpv;
            outp[(size_t)o * HH * WW] = s;
            tp_s[p][o] = tpv;
            sp_s[p][o] = s;
        }
    }
    __syncthreads();

    // Phase 2: dw partials. 240 threads = (chunk:3, kh:5, i:2, o:8).
    // Sliding window over kw: acc[kw] += tp_new[p,o]*x_pad(p,i,kh,kw)
    //                                  + spike[p,o]*tr_pre_new(p,i,kh,kw)
    if (tid < 240) {
        const int o     = tid & 7;
        const int i     = (tid >> 3) & 1;
        const int kh    = (tid >> 4) % 5;
        const int chunk = (tid >> 4) / 5;
        float a0 = 0.f, a1 = 0.f, a2 = 0.f, a3 = 0.f, a4 = 0.f;
        const int r0 = chunk * 3;
        const int r1 = (chunk == 2) ? TH : (r0 + 3);
        for (int px = r0; px < r1; px++) {
            const float* xrow = &xs [i][px + kh][0];
            const float* trow = &trn[i][px + kh][0];
            float x0 = xrow[0], x1 = xrow[1], x2 = xrow[2], x3 = xrow[3];
            float u0 = trow[0], u1 = trow[1], u2 = trow[2], u3 = trow[3];
            const int pb = px * TW;
            #pragma unroll 4
            for (int py = 0; py < TW; py++) {
                float x4  = xrow[py + 4];
                float u4  = trow[py + 4];
                float tpv = tp_s[pb + py][o];
                float spv = sp_s[pb + py][o];
                a0 += tpv*x0 + spv*u0;
                a1 += tpv*x1 + spv*u1;
                a2 += tpv*x2 + spv*u2;
                a3 += tpv*x3 + spv*u3;
                a4 += tpv*x4 + spv*u4;
                x0 = x1; x1 = x2; x2 = x3; x3 = x4;
                u0 = u1; u1 = u2; u2 = u3; u3 = u4;
            }
        }
        const int eb = ((o*CIN + i)*KK + kh)*KK;   // + kw -> [o][i][kh][kw]
        red[(eb + 0)*3 + chunk] = a0;
        red[(eb + 1)*3 + chunk] = a1;
        red[(eb + 2)*3 + chunk] = a2;
        red[(eb + 3)*3 + chunk] = a3;
        red[(eb + 4)*3 + chunk] = a4;
    }
    __syncthreads();

    const int blockLin = blockIdx.x + gridDim.x * (blockIdx.y + gridDim.y * blockIdx.z);
    for (int e = tid; e < NW; e += 256)
        g_part[(size_t)e * NBLK + blockLin] = red[e*3] + red[e*3 + 1] + red[e*3 + 2];
}

// Weight update: deterministic tree-reduction of per-block partials, w -= ETA*dw.
__global__ void k_update() {
    __shared__ float sbuf[128];
    const int e = blockIdx.x;
    float s = 0.f;
    for (int j = threadIdx.x; j < NBLK; j += 128)
        s += g_part[(size_t)e * NBLK + j];
    sbuf[threadIdx.x] = s;
    __syncthreads();
    #pragma unroll
    for (int off = 64; off > 0; off >>= 1) {
        if (threadIdx.x < off) sbuf[threadIdx.x] += sbuf[threadIdx.x + off];
        __syncthreads();
    }
    if (threadIdx.x == 0)
        g_w[e] = g_w[e] - 0.03f * sbuf[0];
}

extern "C" void kernel_launch(void* const* d_in, const int* in_sizes, int n_in,
                              void* d_out, int out_size) {
    const float* x = (const float*)d_in[0];
    const float* w = (const float*)d_in[1];
    if (in_sizes[0] == NW) {  // defensive: swap if metadata order is (weight, x_seq)
        x = (const float*)d_in[1];
        w = (const float*)d_in[0];
    }
    float* out = (float*)d_out;

    k_init<<<2048, 256>>>(w);
    dim3 grid(WW/TW, HH/TH, NB);
    for (int t = 0; t < T_STEPS; t++) {
        k_step<<<grid, 256>>>(x, out, t, t & 1);
        k_update<<<NW, 128>>>();
    }
}